// round 3
// baseline (speedup 1.0000x reference)
#include <cuda_runtime.h>
#include <cuda_bf16.h>

#define NN    1500
#define NEDGE 24000
#define EDIM  64
#define LOOPN 10

// ---------------- device scratch (static, allocation-free) ----------------
__device__ float g_vc[NN * 8];
__device__ float g_goal[8];
__device__ float g_x[NN * EDIM];
__device__ float g_y[NEDGE * EDIM];
__device__ float g_P[NN * EDIM];
__device__ float g_Q[NN * EDIM];
__device__ float g_agg[NN * EDIM];
__device__ float g_A1[EDIM * EDIM], g_B1[EDIM * EDIM];
__device__ float g_A2[EDIM * EDIM], g_B2[EDIM * EDIM];
__device__ float g_Ay[8 * EDIM],   g_By[8 * EDIM];
__device__ int   g_winner[NN * NN];   // 9 MB

#define NEG_INF __int_as_float(0xff800000)

__device__ __forceinline__ void atomicMaxFloat(float* addr, float val) {
    if (val >= 0.0f) atomicMax((int*)addr, __float_as_int(val));
    else             atomicMin((unsigned int*)addr, __float_as_uint(val));
}

#define FMA8(acc, v, w0, w1)                                   \
    {   acc[0] += (v) * (w0).x; acc[1] += (v) * (w0).y;        \
        acc[2] += (v) * (w0).z; acc[3] += (v) * (w0).w;        \
        acc[4] += (v) * (w1).x; acc[5] += (v) * (w1).y;        \
        acc[6] += (v) * (w1).z; acc[7] += (v) * (w1).w; }

// ---------------- prep kernels ----------------

__global__ void k_vc(const float* __restrict__ v, const float* __restrict__ labels) {
    int i = blockIdx.x * blockDim.x + threadIdx.x;
    if (i < NN) {
        #pragma unroll
        for (int j = 0; j < 7; j++) g_vc[i * 8 + j] = v[i * 7 + j];
        g_vc[i * 8 + 7] = labels[i];
    }
}

__global__ void k_goal(const float* __restrict__ labels) {
    __shared__ float bv[256];
    __shared__ int   bi[256];
    int t = threadIdx.x;
    float best = -1e30f; int idx = 0;
    for (int i = t; i < NN; i += 256) {
        float l = labels[i];
        if (l > best) { best = l; idx = i; }
    }
    bv[t] = best; bi[t] = idx;
    __syncthreads();
    for (int s = 128; s > 0; s >>= 1) {
        if (t < s) {
            if (bv[t + s] > bv[t] || (bv[t + s] == bv[t] && bi[t + s] < bi[t])) {
                bv[t] = bv[t + s]; bi[t] = bi[t + s];
            }
        }
        __syncthreads();
    }
    if (t < 8) g_goal[t] = g_vc[bi[0] * 8 + t];
}

// Precompute combined weights:  A = Wd + Wj,  B = Wi - Wd   (row blocks of W1)
__global__ void k_wprep(const float* __restrict__ fxW1, const float* __restrict__ fyW1,
                        const float* __restrict__ hyW1) {
    int t = blockIdx.x * blockDim.x + threadIdx.x;
    if (t < 4096) {
        g_A1[t] = fxW1[t] + fxW1[4096 + t];
        g_B1[t] = fxW1[8192 + t] - fxW1[t];
        g_A2[t] = fyW1[t] + fyW1[4096 + t];
        g_B2[t] = fyW1[8192 + t] - fyW1[t];
        if (t < 512) {
            g_Ay[t] = hyW1[t] + hyW1[512 + t];
            g_By[t] = hyW1[1024 + t] - hyW1[t];
        }
    }
}

// x init: z = [vc, goal, d, d*d] (32) -> relu(z@W1+b1)@W2+b2
__global__ void k_init_x(const float* __restrict__ W1, const float* __restrict__ b1,
                         const float* __restrict__ W2, const float* __restrict__ b2) {
    int i = blockIdx.x;
    int c = threadIdx.x;                 // 64 threads
    __shared__ float z[32], h[64];
    if (c < 8) {
        float vcv = g_vc[i * 8 + c];
        float gl  = g_goal[c];
        float d   = vcv - gl;
        z[c] = vcv; z[8 + c] = gl; z[16 + c] = d; z[24 + c] = d * d;
    }
    __syncthreads();
    float acc = b1[c];
    #pragma unroll
    for (int k = 0; k < 32; k++) acc += z[k] * W1[k * 64 + c];
    h[c] = fmaxf(acc, 0.0f);
    __syncthreads();
    float o = b2[c];
    #pragma unroll 16
    for (int k = 0; k < 64; k++) o += h[k] * W2[k * 64 + c];
    g_x[i * 64 + c] = o;
}

// R = vc@Ay -> g_P (indexed by tgt later), S = vc@By -> g_Q (indexed by src later)
__global__ void k_node8() {
    int i = blockIdx.x, c = threadIdx.x;   // 64 threads
    __shared__ float z[8];
    if (c < 8) z[c] = g_vc[i * 8 + c];
    __syncthreads();
    float r = 0.f, s = 0.f;
    #pragma unroll
    for (int k = 0; k < 8; k++) {
        r += z[k] * g_Ay[k * 64 + c];
        s += z[k] * g_By[k * 64 + c];
    }
    g_P[i * 64 + c] = r;
    g_Q[i * 64 + c] = s;
}

// ---------------- node GEMMs inside the loop ----------------
// Mode A (fx prep): P = x@A1, Q = x@B1, agg = -inf
__global__ void k_node_A() {
    __shared__ float As[4096], Bs[4096], xs[64 * 33];
    int tid = threadIdx.x;
    int i0  = blockIdx.x * 32;
    for (int idx = tid; idx < 4096; idx += 256) { As[idx] = g_A1[idx]; Bs[idx] = g_B1[idx]; }
    for (int idx = tid; idx < 2048; idx += 256) {
        int nl = idx >> 6, k = idx & 63, i = i0 + nl;
        xs[k * 33 + nl] = (i < NN) ? g_x[i * 64 + k] : 0.f;
    }
    __syncthreads();
    int nl = tid >> 3, cg = tid & 7, c0 = cg * 8;
    float ap[8], aq[8];
    #pragma unroll
    for (int j = 0; j < 8; j++) { ap[j] = 0.f; aq[j] = 0.f; }
    #pragma unroll 8
    for (int k = 0; k < 64; k++) {
        float xv = xs[k * 33 + nl];
        float4 a0 = *(const float4*)&As[k * 64 + c0];
        float4 a1 = *(const float4*)&As[k * 64 + c0 + 4];
        float4 b0 = *(const float4*)&Bs[k * 64 + c0];
        float4 b1 = *(const float4*)&Bs[k * 64 + c0 + 4];
        FMA8(ap, xv, a0, a1);
        FMA8(aq, xv, b0, b1);
    }
    int i = i0 + nl;
    if (i < NN) {
        #pragma unroll
        for (int j = 0; j < 8; j++) {
            g_P[i * 64 + c0 + j]   = ap[j];
            g_Q[i * 64 + c0 + j]   = aq[j];
            g_agg[i * 64 + c0 + j] = NEG_INF;
        }
    }
}

// Mode B (after fx agg): x = max(x, agg_fixed); then P = x@A2, Q = x@B2
__global__ void k_node_B() {
    __shared__ float As[4096], Bs[4096], xs[64 * 33];
    int tid = threadIdx.x;
    int i0  = blockIdx.x * 32;
    for (int idx = tid; idx < 4096; idx += 256) { As[idx] = g_A2[idx]; Bs[idx] = g_B2[idx]; }
    int nl = tid >> 3, cg = tid & 7, c0 = cg * 8;
    int i = i0 + nl;
    if (i < NN) {
        #pragma unroll
        for (int j = 0; j < 8; j++) {
            float a = g_agg[i * 64 + c0 + j];
            if (a == NEG_INF) a = 0.f;               // empty segment -> 0
            float xn = fmaxf(g_x[i * 64 + c0 + j], a);
            g_x[i * 64 + c0 + j] = xn;
            xs[(c0 + j) * 33 + nl] = xn;
        }
    } else {
        #pragma unroll
        for (int j = 0; j < 8; j++) xs[(c0 + j) * 33 + nl] = 0.f;
    }
    __syncthreads();
    float ap[8], aq[8];
    #pragma unroll
    for (int j = 0; j < 8; j++) { ap[j] = 0.f; aq[j] = 0.f; }
    #pragma unroll 8
    for (int k = 0; k < 64; k++) {
        float xv = xs[k * 33 + nl];
        float4 a0 = *(const float4*)&As[k * 64 + c0];
        float4 a1 = *(const float4*)&As[k * 64 + c0 + 4];
        float4 b0 = *(const float4*)&Bs[k * 64 + c0];
        float4 b1 = *(const float4*)&Bs[k * 64 + c0 + 4];
        FMA8(ap, xv, a0, a1);
        FMA8(aq, xv, b0, b1);
    }
    if (i < NN) {
        #pragma unroll
        for (int j = 0; j < 8; j++) {
            g_P[i * 64 + c0 + j] = ap[j];
            g_Q[i * 64 + c0 + j] = aq[j];
        }
    }
}

// ---------------- edge kernels ----------------
// h = relu(P[tgt] + Q[src] + b1); out = h@W2 + b2; MODE 0: y = out; MODE 1: y = max(y, out)
template <int MODE>
__global__ void k_edge_y(const float* __restrict__ b1, const float* __restrict__ W2,
                         const float* __restrict__ b2,
                         const int* __restrict__ src, const int* __restrict__ tgt) {
    __shared__ float Ws[4096];
    __shared__ float hs[64 * 33];
    int tid = threadIdx.x;
    int e0  = blockIdx.x * 32;
    for (int idx = tid; idx < 4096; idx += 256) Ws[idx] = W2[idx];
    int el = tid >> 3, cg = tid & 7, c0 = cg * 8;
    int e = e0 + el;
    int s = src[e], t = tgt[e];
    #pragma unroll
    for (int j = 0; j < 8; j++) {
        float h = g_P[t * 64 + c0 + j] + g_Q[s * 64 + c0 + j] + b1[c0 + j];
        hs[(c0 + j) * 33 + el] = fmaxf(h, 0.f);
    }
    __syncthreads();
    float acc[8];
    #pragma unroll
    for (int j = 0; j < 8; j++) acc[j] = b2[c0 + j];
    #pragma unroll 8
    for (int k = 0; k < 64; k++) {
        float hv = hs[k * 33 + el];
        float4 w0 = *(const float4*)&Ws[k * 64 + c0];
        float4 w1 = *(const float4*)&Ws[k * 64 + c0 + 4];
        FMA8(acc, hv, w0, w1);
    }
    if (MODE == 0) {
        #pragma unroll
        for (int j = 0; j < 8; j++) g_y[e * 64 + c0 + j] = acc[j];
    } else {
        #pragma unroll
        for (int j = 0; j < 8; j++) {
            float cur = g_y[e * 64 + c0 + j];
            g_y[e * 64 + c0 + j] = fmaxf(cur, acc[j]);
        }
    }
}

// fx edge step: Y1 = y@Wy; h = relu(P[src] + Q[tgt] + Y1 + b1); msg = h@W2 + b2;
// atomicMax msg into agg[tgt]
__global__ void k_fx_edge(const float* __restrict__ Wy, const float* __restrict__ b1,
                          const float* __restrict__ W2, const float* __restrict__ b2,
                          const int* __restrict__ src, const int* __restrict__ tgt) {
    __shared__ float Wys[4096];
    __shared__ float W2s[4096];
    __shared__ float ys[64 * 33];
    __shared__ float hs[64 * 33];
    int tid = threadIdx.x;
    int e0  = blockIdx.x * 32;
    for (int idx = tid; idx < 4096; idx += 256) { Wys[idx] = Wy[idx]; W2s[idx] = W2[idx]; }
    for (int idx = tid; idx < 2048; idx += 256) {
        int el = idx >> 6, k = idx & 63;
        ys[k * 33 + el] = g_y[(e0 + el) * 64 + k];
    }
    __syncthreads();
    int el = tid >> 3, cg = tid & 7, c0 = cg * 8;
    float acc[8];
    #pragma unroll
    for (int j = 0; j < 8; j++) acc[j] = 0.f;
    #pragma unroll 8
    for (int k = 0; k < 64; k++) {
        float yv = ys[k * 33 + el];
        float4 w0 = *(const float4*)&Wys[k * 64 + c0];
        float4 w1 = *(const float4*)&Wys[k * 64 + c0 + 4];
        FMA8(acc, yv, w0, w1);
    }
    int e = e0 + el;
    int s = src[e], t = tgt[e];
    #pragma unroll
    for (int j = 0; j < 8; j++) {
        float h = acc[j] + g_P[s * 64 + c0 + j] + g_Q[t * 64 + c0 + j] + b1[c0 + j];
        hs[(c0 + j) * 33 + el] = fmaxf(h, 0.f);
    }
    __syncthreads();
    #pragma unroll
    for (int j = 0; j < 8; j++) acc[j] = b2[c0 + j];
    #pragma unroll 8
    for (int k = 0; k < 64; k++) {
        float hv = hs[k * 33 + el];
        float4 w0 = *(const float4*)&W2s[k * 64 + c0];
        float4 w1 = *(const float4*)&W2s[k * 64 + c0 + 4];
        FMA8(acc, hv, w0, w1);
    }
    #pragma unroll
    for (int j = 0; j < 8; j++) atomicMaxFloat(&g_agg[t * 64 + c0 + j], acc[j]);
}

// ---------------- output kernels ----------------
__global__ void k_winner_init() {
    int i = blockIdx.x * blockDim.x + threadIdx.x;
    if (i < NN * NN) g_winner[i] = -1;
}

__global__ void k_winner(const int* __restrict__ src, const int* __restrict__ tgt) {
    int e = blockIdx.x * blockDim.x + threadIdx.x;
    if (e < NEDGE) atomicMax(&g_winner[src[e] * NN + tgt[e]], e);
}

__global__ void k_scatter(const int* __restrict__ src, const int* __restrict__ tgt,
                          float* __restrict__ out) {
    int idx = blockIdx.x * blockDim.x + threadIdx.x;
    if (idx < NEDGE * EDIM) {
        int e = idx >> 6, c = idx & 63;
        int s = src[e], t = tgt[e];
        long long slot = (long long)s * NN + t;
        if (g_winner[slot] == e) out[slot * 64 + c] = g_y[idx];
    }
}

__global__ void k_out_x(float* __restrict__ out) {
    int i = blockIdx.x * blockDim.x + threadIdx.x;
    if (i < NN * EDIM) out[(long long)NN * NN * EDIM + i] = g_x[i];
}

// ---------------- launch ----------------
extern "C" void kernel_launch(void* const* d_in, const int* in_sizes, int n_in,
                              void* d_out, int out_size) {
    const float* v      = (const float*)d_in[0];
    const float* labels = (const float*)d_in[1];
    // d_in[2] obstacles, d_in[3] pos_enc: unused (use_obstacles=False)
    const int*   ei     = (const int*)d_in[4];
    // d_in[5] loop = 10 (compile-time constant for this problem)
    const float* hx_W1 = (const float*)d_in[6],  *hx_b1 = (const float*)d_in[7];
    const float* hx_W2 = (const float*)d_in[8],  *hx_b2 = (const float*)d_in[9];
    const float* hy_W1 = (const float*)d_in[10], *hy_b1 = (const float*)d_in[11];
    const float* hy_W2 = (const float*)d_in[12], *hy_b2 = (const float*)d_in[13];
    const float* fx_W1 = (const float*)d_in[14], *fx_b1 = (const float*)d_in[15];
    const float* fx_W2 = (const float*)d_in[16], *fx_b2 = (const float*)d_in[17];
    const float* fy_W1 = (const float*)d_in[18], *fy_b1 = (const float*)d_in[19];
    const float* fy_W2 = (const float*)d_in[20], *fy_b2 = (const float*)d_in[21];

    const int* src = ei;
    const int* tgt = ei + NEDGE;
    float* out = (float*)d_out;

    // zero the dense [N, N, E] edge_feat region (~576 MB)
    cudaMemsetAsync(d_out, 0, (size_t)NN * NN * EDIM * sizeof(float), 0);
    k_winner_init<<<(NN * NN + 255) / 256, 256>>>();

    k_vc<<<(NN + 255) / 256, 256>>>(v, labels);
    k_goal<<<1, 256>>>(labels);
    k_wprep<<<16, 256>>>(fx_W1, fy_W1, hy_W1);
    k_init_x<<<NN, 64>>>(hx_W1, hx_b1, hx_W2, hx_b2);
    k_node8<<<NN, 64>>>();
    k_edge_y<0><<<NEDGE / 32, 256>>>(hy_b1, hy_W2, hy_b2, src, tgt);

    const int NODE_BLOCKS = (NN + 31) / 32;
    for (int it = 0; it < LOOPN; it++) {
        k_node_A<<<NODE_BLOCKS, 256>>>();
        k_fx_edge<<<NEDGE / 32, 256>>>(fx_W1 + 192 * 64, fx_b1, fx_W2, fx_b2, src, tgt);
        k_node_B<<<NODE_BLOCKS, 256>>>();
        k_edge_y<1><<<NEDGE / 32, 256>>>(fy_b1, fy_W2, fy_b2, src, tgt);
    }

    k_winner<<<(NEDGE + 255) / 256, 256>>>(src, tgt);
    k_scatter<<<(NEDGE * EDIM + 255) / 256, 256>>>(src, tgt, out);
    k_out_x<<<(NN * EDIM + 255) / 256, 256>>>(out);
}